// round 2
// baseline (speedup 1.0000x reference)
#include <cuda_runtime.h>
#include <math.h>

#define BB 128
#define HH 64
#define WW 64
#define AA 9
#define NN (HH*WW*AA)           // 36864 predictions per image
#define KK 100
#define NBUCK 4096
#define CAP 2048
#define THREADS 256
#define DS_ 1024.0f
#define STRIDE_ 64.0f
#define EPS_ 1e-7f

// per-image partial results: {diou_sum, low_sum, high_sum, kept_count}
__device__ float g_scratch[BB * 4];

__device__ __forceinline__ unsigned fkey(float x) {
    unsigned u = __float_as_uint(x);
    return (u & 0x80000000u) ? ~u : (u | 0x80000000u);
}

__global__ __launch_bounds__(THREADS)
void loss_kernel(const float* __restrict__ out5,
                 const float* __restrict__ tboxes,
                 const float* __restrict__ anchors)
{
    __shared__ unsigned s_hist[NBUCK];
    __shared__ unsigned long long s_cand[CAP];
    __shared__ unsigned s_part[THREADS];
    __shared__ float s_bx1[KK], s_by1[KK], s_bx2[KK], s_by2[KK], s_ba[KK], s_val[KK];
    __shared__ float s_tx1[KK], s_ty1[KK], s_tx2[KK], s_ty2[KK];
    __shared__ unsigned s_sup[KK][4];
    __shared__ unsigned s_kw[4];
    __shared__ int s_cnt, s_bsel;
    __shared__ float s_anc[AA * 2];
    __shared__ float s_red[3][THREADS / 32];

    const int tid = threadIdx.x;
    const int img = blockIdx.x;
    const float* __restrict__ ip = out5 + (size_t)img * NN * 5;

    if (tid < AA * 2) s_anc[tid] = anchors[tid];
    for (int i = tid; i < NBUCK; i += THREADS) s_hist[i] = 0;
    if (tid == 0) { s_cnt = 0; s_kw[0] = s_kw[1] = s_kw[2] = s_kw[3] = 0; }
    for (int i = tid; i < KK * 4; i += THREADS) ((unsigned*)s_sup)[i] = 0;
    __syncthreads();

    // ---- pass 1: histogram of logit order-keys (top 12 bits) ----
    for (int e = tid; e < NN; e += THREADS) {
        float x = __ldg(&ip[e * 5 + 4]);
        atomicAdd(&s_hist[fkey(x) >> 20], 1u);
    }
    __syncthreads();

    // partial sums (16 buckets per thread) then serial suffix scan by thread 0
    {
        unsigned s = 0;
        int base = tid * (NBUCK / THREADS);
        #pragma unroll
        for (int j = 0; j < NBUCK / THREADS; j++) s += s_hist[base + j];
        s_part[tid] = s;
    }
    __syncthreads();
    if (tid == 0) {
        unsigned cum = 0; int seg = 0;
        for (int t = THREADS - 1; t >= 0; t--) {
            if (cum + s_part[t] >= KK) { seg = t; break; }
            cum += s_part[t];
        }
        int bsel = seg * (NBUCK / THREADS);
        for (int b = seg * (NBUCK / THREADS) + (NBUCK / THREADS) - 1;
             b >= seg * (NBUCK / THREADS); b--) {
            cum += s_hist[b];
            if (cum >= KK) { bsel = b; break; }
        }
        s_bsel = bsel;
    }
    __syncthreads();
    const int bsel = s_bsel;

    // ---- pass 2: collect candidates; composite = (conf_key << 32) | ~idx ----
    for (int e = tid; e < NN; e += THREADS) {
        float x = __ldg(&ip[e * 5 + 4]);
        if ((int)(fkey(x) >> 20) >= bsel) {
            int pos = atomicAdd(&s_cnt, 1);
            if (pos < CAP) {
                float conf = 1.0f / (1.0f + expf(-x));   // conf > 0 always
                unsigned ck = __float_as_uint(conf) ^ 0x80000000u;
                s_cand[pos] = ((unsigned long long)ck << 32)
                            | (unsigned)(0xFFFFFFFFu - (unsigned)e);
            }
        }
    }
    __syncthreads();
    int C = min(s_cnt, CAP);
    int P = 128;
    while (P < C) P <<= 1;
    for (int i = C + tid; i < P; i += THREADS) s_cand[i] = 0ull;
    __syncthreads();

    // ---- bitonic sort descending (conf desc, index asc) ----
    for (int k = 2; k <= P; k <<= 1) {
        for (int j = k >> 1; j > 0; j >>= 1) {
            for (int i = tid; i < P; i += THREADS) {
                int ixj = i ^ j;
                if (ixj > i) {
                    unsigned long long va = s_cand[i], vb = s_cand[ixj];
                    bool desc = ((i & k) == 0);
                    if ((va < vb) == desc) { s_cand[i] = vb; s_cand[ixj] = va; }
                }
            }
            __syncthreads();
        }
    }

    // ---- build top-K boxes (clip + fix), cmask, targets ----
    if (tid < KK) {
        unsigned long long v = s_cand[tid];
        unsigned ck = (unsigned)(v >> 32);
        float conf = __uint_as_float(ck ^ 0x80000000u);
        int e = (int)(0xFFFFFFFFu - (unsigned)(v & 0xFFFFFFFFull));
        float o0 = ip[e * 5 + 0], o1 = ip[e * 5 + 1];
        float o2 = ip[e * 5 + 2], o3 = ip[e * 5 + 3];
        int a = e % AA;
        int w = (e / AA) % WW;
        int h = e / (AA * WW);
        float px = (1.0f / (1.0f + expf(-o0)) + (float)w) * STRIDE_;
        float py = (1.0f / (1.0f + expf(-o1)) + (float)h) * STRIDE_;
        float pw = expf(o2) * s_anc[a * 2 + 0] * DS_;
        float ph = expf(o3) * s_anc[a * 2 + 1] * DS_;
        float c0 = px - pw * 0.5f, c1 = py - ph * 0.5f;
        float c2 = px + pw * 0.5f, c3 = py + ph * 0.5f;
        c0 = fminf(fmaxf(c0, 0.0f), DS_); c1 = fminf(fmaxf(c1, 0.0f), DS_);
        c2 = fminf(fmaxf(c2, 0.0f), DS_); c3 = fminf(fmaxf(c3, 0.0f), DS_);
        float x1 = fminf(c0, c2), x2 = fmaxf(c0, c2);
        float y1 = fminf(c1, c3), y2 = fmaxf(c1, c3);
        if (x1 == x2) x2 = x1 + 1.0f;
        if (y1 == y2) y2 = y1 + 1.0f;
        s_bx1[tid] = x1; s_by1[tid] = y1; s_bx2[tid] = x2; s_by2[tid] = y2;
        s_ba[tid] = (x2 - x1) * (y2 - y1);
        s_val[tid] = conf;
        if (conf >= 0.5f) atomicOr(&s_kw[tid >> 5], 1u << (tid & 31));

        const float* tp = tboxes + ((size_t)img * KK + tid) * 4;
        float t0 = fminf(fmaxf(tp[0], 0.0f), DS_);
        float t1 = fminf(fmaxf(tp[1], 0.0f), DS_);
        float t2 = fminf(fmaxf(tp[2], 0.0f), DS_);
        float t3 = fminf(fmaxf(tp[3], 0.0f), DS_);
        float tx1 = fminf(t0, t2), tx2 = fmaxf(t0, t2);
        float ty1 = fminf(t1, t3), ty2 = fmaxf(t1, t3);
        if (tx1 == tx2) tx2 = tx1 + 1.0f;
        if (ty1 == ty2) ty2 = ty1 + 1.0f;
        s_tx1[tid] = tx1; s_ty1[tid] = ty1; s_tx2[tid] = tx2; s_ty2[tid] = ty2;
    }
    __syncthreads();

    // ---- pairwise pred-pred suppression bitmask (parallel) ----
    for (int p = tid; p < KK * KK; p += THREADS) {
        int i = p / KK, j = p % KK;
        if (j > i) {
            float lx = fmaxf(s_bx1[i], s_bx1[j]);
            float ly = fmaxf(s_by1[i], s_by1[j]);
            float rx = fminf(s_bx2[i], s_bx2[j]);
            float ry = fminf(s_by2[i], s_by2[j]);
            float iw = fmaxf(rx - lx, 0.0f), ih = fmaxf(ry - ly, 0.0f);
            float inter = iw * ih;
            float iou = inter / (s_ba[i] + s_ba[j] - inter + EPS_);
            if (iou > 0.5f) atomicOr(&s_sup[i][j >> 5], 1u << (j & 31));
        }
    }
    __syncthreads();

    // ---- greedy NMS sweep (exact reference semantics), serial in thread 0 ----
    if (tid == 0) {
        unsigned kw0 = s_kw[0], kw1 = s_kw[1], kw2 = s_kw[2], kw3 = s_kw[3];
        for (int i = 0; i < KK; i++) {
            unsigned wv = (i < 32) ? kw0 : (i < 64) ? kw1 : (i < 96) ? kw2 : kw3;
            if ((wv >> (i & 31)) & 1u) {
                kw0 &= ~s_sup[i][0]; kw1 &= ~s_sup[i][1];
                kw2 &= ~s_sup[i][2]; kw3 &= ~s_sup[i][3];
            }
        }
        s_kw[0] = kw0; s_kw[1] = kw1; s_kw[2] = kw2; s_kw[3] = kw3;
    }
    __syncthreads();

    // ---- per-target DIoU loss ----
    float diou = 0.0f, lowv = 0.0f, highv = 0.0f;
    if (tid < KK) {
        unsigned kw[4] = { s_kw[0], s_kw[1], s_kw[2], s_kw[3] };
        float tx1 = s_tx1[tid], ty1 = s_ty1[tid], tx2 = s_tx2[tid], ty2 = s_ty2[tid];
        float ta = (tx2 - tx1) * (ty2 - ty1);
        float maxv = -1.0f; int best = 0;
        for (int p = 0; p < KK; p++) {
            float kf = ((kw[p >> 5] >> (p & 31)) & 1u) ? 1.0f : 0.0f;
            float lx = fmaxf(s_bx1[p], tx1);
            float ly = fmaxf(s_by1[p], ty1);
            float rx = fminf(s_bx2[p], tx2);
            float ry = fminf(s_by2[p], ty2);
            float iw = fmaxf(rx - lx, 0.0f), ih = fmaxf(ry - ly, 0.0f);
            float inter = iw * ih;
            float iou = inter / (s_ba[p] + ta - inter + EPS_);
            float v = iou * kf;
            if (v > maxv) { maxv = v; best = p; }   // first occurrence wins
        }
        float max_iou = fmaxf(maxv, 0.0f);
        float pbx1 = s_bx1[best], pby1 = s_by1[best];
        float pbx2 = s_bx2[best], pby2 = s_by2[best];
        float pcx = (pbx1 + pbx2) * 0.5f, pcy = (pby1 + pby2) * 0.5f;
        float tcx = (tx1 + tx2) * 0.5f,  tcy = (ty1 + ty2) * 0.5f;
        float cd = (pcx - tcx) * (pcx - tcx) + (pcy - tcy) * (pcy - tcy);
        float ex1 = fminf(pbx1, tx1), ey1 = fminf(pby1, ty1);
        float ex2 = fmaxf(pbx2, tx2), ey2 = fmaxf(pby2, ty2);
        float dg = (ex2 - ex1) * (ex2 - ex1) + (ey2 - ey1) * (ey2 - ey1);
        diou = 1.0f - (max_iou - cd / (dg + EPS_));

        float kfr = ((s_kw[tid >> 5] >> (tid & 31)) & 1u) ? 1.0f : 0.0f;
        float val = s_val[tid];
        lowv  = fmaxf(-val, 0.0f) * kfr;          // exactly 0 for sigmoid outputs
        highv = fmaxf(val - 1.0f, 0.0f) * kfr;    // exactly 0 for sigmoid outputs
    }

    // deterministic reduction: warp shuffles + fixed-order smem combine
    #pragma unroll
    for (int off = 16; off; off >>= 1) {
        diou  += __shfl_down_sync(0xFFFFFFFFu, diou,  off);
        lowv  += __shfl_down_sync(0xFFFFFFFFu, lowv,  off);
        highv += __shfl_down_sync(0xFFFFFFFFu, highv, off);
    }
    if ((tid & 31) == 0) {
        s_red[0][tid >> 5] = diou;
        s_red[1][tid >> 5] = lowv;
        s_red[2][tid >> 5] = highv;
    }
    __syncthreads();
    if (tid == 0) {
        float d = 0.0f, l = 0.0f, h = 0.0f;
        #pragma unroll
        for (int w = 0; w < THREADS / 32; w++) {
            d += s_red[0][w]; l += s_red[1][w]; h += s_red[2][w];
        }
        float cnt = (float)(__popc(s_kw[0]) + __popc(s_kw[1]) +
                            __popc(s_kw[2]) + __popc(s_kw[3]));
        g_scratch[img * 4 + 0] = d;
        g_scratch[img * 4 + 1] = l;
        g_scratch[img * 4 + 2] = h;
        g_scratch[img * 4 + 3] = cnt;
    }
}

__global__ __launch_bounds__(128)
void finalize_kernel(float* __restrict__ out)
{
    __shared__ float sw[4][4];
    int tid = threadIdx.x;
    float d = 0.0f, l = 0.0f, h = 0.0f, c = 0.0f;
    if (tid < BB) {
        d = g_scratch[tid * 4 + 0];
        l = g_scratch[tid * 4 + 1];
        h = g_scratch[tid * 4 + 2];
        c = g_scratch[tid * 4 + 3];
    }
    #pragma unroll
    for (int off = 16; off; off >>= 1) {
        d += __shfl_down_sync(0xFFFFFFFFu, d, off);
        l += __shfl_down_sync(0xFFFFFFFFu, l, off);
        h += __shfl_down_sync(0xFFFFFFFFu, h, off);
        c += __shfl_down_sync(0xFFFFFFFFu, c, off);
    }
    if ((tid & 31) == 0) {
        sw[0][tid >> 5] = d; sw[1][tid >> 5] = l;
        sw[2][tid >> 5] = h; sw[3][tid >> 5] = c;
    }
    __syncthreads();
    if (tid == 0) {
        float D = 0.0f, L = 0.0f, H = 0.0f, Cn = 0.0f;
        #pragma unroll
        for (int w = 0; w < 4; w++) { D += sw[0][w]; L += sw[1][w]; H += sw[2][w]; Cn += sw[3][w]; }
        float n = fmaxf(Cn, 1.0f);
        out[0] = D / (float)(BB * KK) + L / n + 0.5f * (H / n);
    }
}

extern "C" void kernel_launch(void* const* d_in, const int* in_sizes, int n_in,
                              void* d_out, int out_size)
{
    const float* output  = (const float*)d_in[0];   // (128,64,64,9,5) fp32
    const float* tboxes  = (const float*)d_in[1];   // (128,100,4) fp32
    const float* anchors = (const float*)d_in[2];   // (9,2) fp32
    float* out = (float*)d_out;

    loss_kernel<<<BB, THREADS>>>(output, tboxes, anchors);
    finalize_kernel<<<1, 128>>>(out);
}

// round 4
// speedup vs baseline: 1.2891x; 1.2891x over previous
#include <cuda_runtime.h>
#include <math.h>

#define BB 128
#define HH 64
#define WW 64
#define AA 9
#define NN (HH*WW*AA)           // 36864 predictions per image
#define NG (NN/4)               // 9216 groups of 4 records (20 floats = 5 float4)
#define KK 100
#define NBUCK 4096
#define CAP 2048
#define THREADS 256
#define DS_ 1024.0f
#define STRIDE_ 64.0f
#define EPS_ 1e-7f
#define T0_ 1.25f               // static logit collect-threshold (fallback-guarded)

// per-image partial results: {diou_sum, low_sum, high_sum, kept_count}
__device__ float g_scratch[BB * 4];
__device__ unsigned g_done;     // zero-initialized; last block resets it

__device__ __forceinline__ unsigned fkey(float x) {
    unsigned u = __float_as_uint(x);
    return (u & 0x80000000u) ? ~u : (u | 0x80000000u);
}

__device__ __forceinline__ unsigned long long make_cand(float x, int e) {
    float conf = 1.0f / (1.0f + __expf(-x));        // conf in (0,1)
    unsigned ck = __float_as_uint(conf) ^ 0x80000000u; // order-preserving (conf>0)
    return ((unsigned long long)ck << 32) | (unsigned)(0xFFFFFFFFu - (unsigned)e);
}

__global__ __launch_bounds__(THREADS)
void loss_kernel(const float* __restrict__ out5,
                 const float* __restrict__ tboxes,
                 const float* __restrict__ anchors,
                 float* __restrict__ out)
{
    __shared__ unsigned s_hist[NBUCK];              // fallback only
    __shared__ unsigned long long s_cand[CAP];
    __shared__ unsigned s_part[THREADS];            // fallback only
    __shared__ float s_bx1[KK], s_by1[KK], s_bx2[KK], s_by2[KK], s_ba[KK], s_val[KK];
    __shared__ float s_tx1[KK], s_ty1[KK], s_tx2[KK], s_ty2[KK];
    __shared__ unsigned s_sup[KK][4];
    __shared__ unsigned s_kw[4];
    __shared__ int s_cnt, s_bsel, s_last;
    __shared__ float s_anc[AA * 2];
    __shared__ float s_red[3][THREADS / 32];

    const int tid = threadIdx.x;
    const int img = blockIdx.x;
    const float* __restrict__ ip = out5 + (size_t)img * NN * 5;
    const float4* __restrict__ ip4 = (const float4*)ip;

    if (tid < AA * 2) s_anc[tid] = anchors[tid];
    if (tid == 0) { s_cnt = 0; s_kw[0] = s_kw[1] = s_kw[2] = s_kw[3] = 0; }
    for (int i = tid; i < KK * 4; i += THREADS) ((unsigned*)s_sup)[i] = 0;
    __syncthreads();

    // ---- single streaming pass: collect candidates with logit > T0 ----
    // Record r of group g: conf at float 20g+5r+4.
    // r=0 -> f4[5g+1].x  r=1 -> f4[5g+2].y  r=2 -> f4[5g+3].z  r=3 -> f4[5g+4].w
    #pragma unroll 4
    for (int g = tid; g < NG; g += THREADS) {
        const float4* p = ip4 + (size_t)g * 5;
        float4 v1 = p[1], v2 = p[2], v3 = p[3], v4 = p[4];
        int e0 = g * 4;
        if (v1.x > T0_) { int q = atomicAdd(&s_cnt, 1); if (q < CAP) s_cand[q] = make_cand(v1.x, e0 + 0); }
        if (v2.y > T0_) { int q = atomicAdd(&s_cnt, 1); if (q < CAP) s_cand[q] = make_cand(v2.y, e0 + 1); }
        if (v3.z > T0_) { int q = atomicAdd(&s_cnt, 1); if (q < CAP) s_cand[q] = make_cand(v3.z, e0 + 2); }
        if (v4.w > T0_) { int q = atomicAdd(&s_cnt, 1); if (q < CAP) s_cand[q] = make_cand(v4.w, e0 + 3); }
    }
    __syncthreads();

    // ---- fallback: exact histogram top-K path (never taken for typical inputs) ----
    if (s_cnt < KK || s_cnt > CAP) {
        for (int i = tid; i < NBUCK; i += THREADS) s_hist[i] = 0;
        if (tid == 0) s_cnt = 0;
        __syncthreads();
        for (int e = tid; e < NN; e += THREADS) {
            float x = ip[e * 5 + 4];
            atomicAdd(&s_hist[fkey(x) >> 20], 1u);
        }
        __syncthreads();
        {
            unsigned s = 0;
            int base = tid * (NBUCK / THREADS);
            #pragma unroll
            for (int j = 0; j < NBUCK / THREADS; j++) s += s_hist[base + j];
            s_part[tid] = s;
        }
        __syncthreads();
        if (tid == 0) {
            unsigned cum = 0; int seg = 0;
            for (int t = THREADS - 1; t >= 0; t--) {
                if (cum + s_part[t] >= KK) { seg = t; break; }
                cum += s_part[t];
            }
            int bsel = seg * (NBUCK / THREADS);
            for (int b = seg * (NBUCK / THREADS) + (NBUCK / THREADS) - 1;
                 b >= seg * (NBUCK / THREADS); b--) {
                cum += s_hist[b];
                if (cum >= KK) { bsel = b; break; }
            }
            s_bsel = bsel;
        }
        __syncthreads();
        const int bsel = s_bsel;
        for (int e = tid; e < NN; e += THREADS) {
            float x = ip[e * 5 + 4];
            if ((int)(fkey(x) >> 20) >= bsel) {
                int pos = atomicAdd(&s_cnt, 1);
                if (pos < CAP) s_cand[pos] = make_cand(x, e);
            }
        }
        __syncthreads();
    }

    int C = min(s_cnt, CAP);
    int P = 128;
    while (P < C) P <<= 1;
    if (P > CAP) P = CAP;
    for (int i = C + tid; i < P; i += THREADS) s_cand[i] = 0ull;
    __syncthreads();

    // ---- bitonic sort descending (conf desc, index asc) ----
    for (int k = 2; k <= P; k <<= 1) {
        for (int j = k >> 1; j > 0; j >>= 1) {
            for (int i = tid; i < P; i += THREADS) {
                int ixj = i ^ j;
                if (ixj > i) {
                    unsigned long long va = s_cand[i], vb = s_cand[ixj];
                    bool desc = ((i & k) == 0);
                    if ((va < vb) == desc) { s_cand[i] = vb; s_cand[ixj] = va; }
                }
            }
            __syncthreads();
        }
    }

    // ---- build top-K boxes (clip + fix), cmask, targets ----
    if (tid < KK) {
        unsigned long long v = s_cand[tid];
        unsigned ck = (unsigned)(v >> 32);
        float conf = __uint_as_float(ck ^ 0x80000000u);
        int e = (int)(0xFFFFFFFFu - (unsigned)(v & 0xFFFFFFFFull));
        float o0 = ip[e * 5 + 0], o1 = ip[e * 5 + 1];
        float o2 = ip[e * 5 + 2], o3 = ip[e * 5 + 3];
        int a = e % AA;
        int w = (e / AA) % WW;
        int h = e / (AA * WW);
        float px = (1.0f / (1.0f + __expf(-o0)) + (float)w) * STRIDE_;
        float py = (1.0f / (1.0f + __expf(-o1)) + (float)h) * STRIDE_;
        float pw = __expf(o2) * s_anc[a * 2 + 0] * DS_;
        float ph = __expf(o3) * s_anc[a * 2 + 1] * DS_;
        float c0 = px - pw * 0.5f, c1 = py - ph * 0.5f;
        float c2 = px + pw * 0.5f, c3 = py + ph * 0.5f;
        c0 = fminf(fmaxf(c0, 0.0f), DS_); c1 = fminf(fmaxf(c1, 0.0f), DS_);
        c2 = fminf(fmaxf(c2, 0.0f), DS_); c3 = fminf(fmaxf(c3, 0.0f), DS_);
        float x1 = fminf(c0, c2), x2 = fmaxf(c0, c2);
        float y1 = fminf(c1, c3), y2 = fmaxf(c1, c3);
        if (x1 == x2) x2 = x1 + 1.0f;
        if (y1 == y2) y2 = y1 + 1.0f;
        s_bx1[tid] = x1; s_by1[tid] = y1; s_bx2[tid] = x2; s_by2[tid] = y2;
        s_ba[tid] = (x2 - x1) * (y2 - y1);
        s_val[tid] = conf;
        if (conf >= 0.5f) atomicOr(&s_kw[tid >> 5], 1u << (tid & 31));

        const float* tp = tboxes + ((size_t)img * KK + tid) * 4;
        float t0 = fminf(fmaxf(tp[0], 0.0f), DS_);
        float t1 = fminf(fmaxf(tp[1], 0.0f), DS_);
        float t2 = fminf(fmaxf(tp[2], 0.0f), DS_);
        float t3 = fminf(fmaxf(tp[3], 0.0f), DS_);
        float tx1 = fminf(t0, t2), tx2 = fmaxf(t0, t2);
        float ty1 = fminf(t1, t3), ty2 = fmaxf(t1, t3);
        if (tx1 == tx2) tx2 = tx1 + 1.0f;
        if (ty1 == ty2) ty2 = ty1 + 1.0f;
        s_tx1[tid] = tx1; s_ty1[tid] = ty1; s_tx2[tid] = tx2; s_ty2[tid] = ty2;
    }
    __syncthreads();

    // ---- pairwise pred-pred suppression bitmask (parallel) ----
    for (int p = tid; p < KK * KK; p += THREADS) {
        int i = p / KK, j = p % KK;
        if (j > i) {
            float lx = fmaxf(s_bx1[i], s_bx1[j]);
            float ly = fmaxf(s_by1[i], s_by1[j]);
            float rx = fminf(s_bx2[i], s_bx2[j]);
            float ry = fminf(s_by2[i], s_by2[j]);
            float iw = fmaxf(rx - lx, 0.0f), ih = fmaxf(ry - ly, 0.0f);
            float inter = iw * ih;
            float iou = inter / (s_ba[i] + s_ba[j] - inter + EPS_);
            if (iou > 0.5f) atomicOr(&s_sup[i][j >> 5], 1u << (j & 31));
        }
    }
    __syncthreads();

    // ---- greedy NMS sweep (exact reference semantics), serial in thread 0 ----
    if (tid == 0) {
        unsigned kw0 = s_kw[0], kw1 = s_kw[1], kw2 = s_kw[2], kw3 = s_kw[3];
        for (int i = 0; i < KK; i++) {
            unsigned wv = (i < 32) ? kw0 : (i < 64) ? kw1 : (i < 96) ? kw2 : kw3;
            if ((wv >> (i & 31)) & 1u) {
                kw0 &= ~s_sup[i][0]; kw1 &= ~s_sup[i][1];
                kw2 &= ~s_sup[i][2]; kw3 &= ~s_sup[i][3];
            }
        }
        s_kw[0] = kw0; s_kw[1] = kw1; s_kw[2] = kw2; s_kw[3] = kw3;
    }
    __syncthreads();

    // ---- per-target DIoU loss ----
    float diou = 0.0f, lowv = 0.0f, highv = 0.0f;
    if (tid < KK) {
        unsigned kw[4] = { s_kw[0], s_kw[1], s_kw[2], s_kw[3] };
        float tx1 = s_tx1[tid], ty1 = s_ty1[tid], tx2 = s_tx2[tid], ty2 = s_ty2[tid];
        float ta = (tx2 - tx1) * (ty2 - ty1);
        float maxv = -1.0f; int best = 0;
        for (int p = 0; p < KK; p++) {
            float kf = ((kw[p >> 5] >> (p & 31)) & 1u) ? 1.0f : 0.0f;
            float lx = fmaxf(s_bx1[p], tx1);
            float ly = fmaxf(s_by1[p], ty1);
            float rx = fminf(s_bx2[p], tx2);
            float ry = fminf(s_by2[p], ty2);
            float iw = fmaxf(rx - lx, 0.0f), ih = fmaxf(ry - ly, 0.0f);
            float inter = iw * ih;
            float iou = inter / (s_ba[p] + ta - inter + EPS_);
            float v = iou * kf;
            if (v > maxv) { maxv = v; best = p; }   // first occurrence wins
        }
        float max_iou = fmaxf(maxv, 0.0f);
        float pbx1 = s_bx1[best], pby1 = s_by1[best];
        float pbx2 = s_bx2[best], pby2 = s_by2[best];
        float pcx = (pbx1 + pbx2) * 0.5f, pcy = (pby1 + pby2) * 0.5f;
        float tcx = (tx1 + tx2) * 0.5f,  tcy = (ty1 + ty2) * 0.5f;
        float cd = (pcx - tcx) * (pcx - tcx) + (pcy - tcy) * (pcy - tcy);
        float ex1 = fminf(pbx1, tx1), ey1 = fminf(pby1, ty1);
        float ex2 = fmaxf(pbx2, tx2), ey2 = fmaxf(pby2, ty2);
        float dg = (ex2 - ex1) * (ex2 - ex1) + (ey2 - ey1) * (ey2 - ey1);
        diou = 1.0f - (max_iou - cd / (dg + EPS_));

        float kfr = ((s_kw[tid >> 5] >> (tid & 31)) & 1u) ? 1.0f : 0.0f;
        float val = s_val[tid];
        lowv  = fmaxf(-val, 0.0f) * kfr;
        highv = fmaxf(val - 1.0f, 0.0f) * kfr;
    }

    // deterministic reduction: warp shuffles + fixed-order smem combine
    #pragma unroll
    for (int off = 16; off; off >>= 1) {
        diou  += __shfl_down_sync(0xFFFFFFFFu, diou,  off);
        lowv  += __shfl_down_sync(0xFFFFFFFFu, lowv,  off);
        highv += __shfl_down_sync(0xFFFFFFFFu, highv, off);
    }
    if ((tid & 31) == 0) {
        s_red[0][tid >> 5] = diou;
        s_red[1][tid >> 5] = lowv;
        s_red[2][tid >> 5] = highv;
    }
    __syncthreads();
    if (tid == 0) {
        float d = 0.0f, l = 0.0f, h = 0.0f;
        #pragma unroll
        for (int w = 0; w < THREADS / 32; w++) {
            d += s_red[0][w]; l += s_red[1][w]; h += s_red[2][w];
        }
        float cnt = (float)(__popc(s_kw[0]) + __popc(s_kw[1]) +
                            __popc(s_kw[2]) + __popc(s_kw[3]));
        g_scratch[img * 4 + 0] = d;
        g_scratch[img * 4 + 1] = l;
        g_scratch[img * 4 + 2] = h;
        g_scratch[img * 4 + 3] = cnt;
        __threadfence();
        unsigned t = atomicAdd(&g_done, 1u);
        s_last = (t == BB - 1) ? 1 : 0;
    }
    __syncthreads();

    // ---- last block performs the global reduction (fused finalize) ----
    if (s_last) {
        float d = 0.0f, l = 0.0f, h = 0.0f, c = 0.0f;
        if (tid < BB) {
            d = g_scratch[tid * 4 + 0];
            l = g_scratch[tid * 4 + 1];
            h = g_scratch[tid * 4 + 2];
            c = g_scratch[tid * 4 + 3];
        }
        #pragma unroll
        for (int off = 16; off; off >>= 1) {
            d += __shfl_down_sync(0xFFFFFFFFu, d, off);
            l += __shfl_down_sync(0xFFFFFFFFu, l, off);
            h += __shfl_down_sync(0xFFFFFFFFu, h, off);
            c += __shfl_down_sync(0xFFFFFFFFu, c, off);
        }
        if ((tid & 31) == 0) {
            s_red[0][tid >> 5] = d;
            s_red[1][tid >> 5] = l;
            s_red[2][tid >> 5] = h;
            s_part[tid >> 5]   = __float_as_uint(c);
        }
        __syncthreads();
        if (tid == 0) {
            float D = 0.0f, L = 0.0f, H = 0.0f, Cn = 0.0f;
            #pragma unroll
            for (int w = 0; w < THREADS / 32; w++) {
                D += s_red[0][w]; L += s_red[1][w]; H += s_red[2][w];
                Cn += __uint_as_float(s_part[w]);
            }
            float n = fmaxf(Cn, 1.0f);
            out[0] = D / (float)(BB * KK) + L / n + 0.5f * (H / n);
            g_done = 0;                 // reset for next graph replay
        }
    }
}

extern "C" void kernel_launch(void* const* d_in, const int* in_sizes, int n_in,
                              void* d_out, int out_size)
{
    const float* output  = (const float*)d_in[0];   // (128,64,64,9,5) fp32
    const float* tboxes  = (const float*)d_in[1];   // (128,100,4) fp32
    const float* anchors = (const float*)d_in[2];   // (9,2) fp32
    float* out = (float*)d_out;

    loss_kernel<<<BB, THREADS>>>(output, tboxes, anchors, out);
}

// round 5
// speedup vs baseline: 1.3113x; 1.0172x over previous
#include <cuda_runtime.h>
#include <math.h>

#define BB 128
#define HH 64
#define WW 64
#define AA 9
#define NN (HH*WW*AA)           // 36864 predictions per image
#define KK 100
#define NBUCK 4096
#define CAP 1024                // candidate capacity per image
#define SPLIT 8                 // collect CTAs per image
#define NSEG (NN/SPLIT)         // 4608 elements per collect CTA
#define THREADS 256
#define DS_ 1024.0f
#define STRIDE_ 64.0f
#define EPS_ 1e-7f
#define T0_ 1.25f               // static logit collect-threshold (fallback-guarded)

// globals (zero-initialized at load; kernels self-reset for graph replay)
__device__ unsigned long long g_cand[BB][CAP];
__device__ int g_cnt[BB];
__device__ float g_scratch[BB * 4];
__device__ unsigned g_done;

__device__ __forceinline__ unsigned fkey(float x) {
    unsigned u = __float_as_uint(x);
    return (u & 0x80000000u) ? ~u : (u | 0x80000000u);
}

__device__ __forceinline__ unsigned long long make_cand(float x, int e) {
    float conf = 1.0f / (1.0f + __expf(-x));           // conf in (0,1)
    unsigned ck = __float_as_uint(conf) ^ 0x80000000u; // order-preserving (conf>0)
    return ((unsigned long long)ck << 32) | (unsigned)(0xFFFFFFFFu - (unsigned)e);
}

// ---- kernel A: high-occupancy candidate collection (conf-only stream) ----
__global__ __launch_bounds__(THREADS)
void collect_kernel(const float* __restrict__ out5)
{
    const int img = blockIdx.x / SPLIT;
    const int seg = blockIdx.x % SPLIT;
    const float* __restrict__ ip = out5 + (size_t)img * NN * 5;
    const int base = seg * NSEG;

    #pragma unroll 6
    for (int i = threadIdx.x; i < NSEG; i += THREADS) {
        int e = base + i;
        float x = __ldg(&ip[(size_t)e * 5 + 4]);
        if (x > T0_) {
            int q = atomicAdd(&g_cnt[img], 1);
            if (q < CAP) g_cand[img][q] = make_cand(x, e);
        }
    }
}

// ---- kernel B: per-image sort + NMS + DIoU + fused finalize ----
__global__ __launch_bounds__(THREADS)
void loss_kernel(const float* __restrict__ out5,
                 const float* __restrict__ tboxes,
                 const float* __restrict__ anchors,
                 float* __restrict__ out)
{
    __shared__ unsigned s_hist[NBUCK];              // fallback only
    __shared__ unsigned long long s_cand[CAP];
    __shared__ unsigned s_part[THREADS];            // fallback / finalize scratch
    __shared__ float s_bx1[KK], s_by1[KK], s_bx2[KK], s_by2[KK], s_ba[KK], s_val[KK];
    __shared__ float s_tx1[KK], s_ty1[KK], s_tx2[KK], s_ty2[KK];
    __shared__ unsigned s_sup[KK][4];
    __shared__ unsigned s_kw[4];
    __shared__ int s_cnt, s_bsel, s_last;
    __shared__ float s_anc[AA * 2];
    __shared__ float s_red[3][THREADS / 32];

    const int tid = threadIdx.x;
    const int img = blockIdx.x;
    const float* __restrict__ ip = out5 + (size_t)img * NN * 5;

    if (tid < AA * 2) s_anc[tid] = anchors[tid];
    if (tid == 0) { s_kw[0] = s_kw[1] = s_kw[2] = s_kw[3] = 0; }
    for (int i = tid; i < KK * 4; i += THREADS) ((unsigned*)s_sup)[i] = 0;

    // pull candidate count + entries from global
    const int gcnt = g_cnt[img];
    if (tid == 0) s_cnt = gcnt;
    {
        int C0 = min(gcnt, CAP);
        for (int i = tid; i < C0; i += THREADS) s_cand[i] = g_cand[img][i];
    }
    __syncthreads();

    // ---- fallback: exact histogram top-K path (never taken for typical inputs) ----
    if (gcnt < KK || gcnt > CAP) {
        for (int i = tid; i < NBUCK; i += THREADS) s_hist[i] = 0;
        if (tid == 0) s_cnt = 0;
        __syncthreads();
        for (int e = tid; e < NN; e += THREADS) {
            float x = ip[(size_t)e * 5 + 4];
            atomicAdd(&s_hist[fkey(x) >> 20], 1u);
        }
        __syncthreads();
        {
            unsigned s = 0;
            int base = tid * (NBUCK / THREADS);
            #pragma unroll
            for (int j = 0; j < NBUCK / THREADS; j++) s += s_hist[base + j];
            s_part[tid] = s;
        }
        __syncthreads();
        if (tid == 0) {
            unsigned cum = 0; int seg = 0;
            for (int t = THREADS - 1; t >= 0; t--) {
                if (cum + s_part[t] >= KK) { seg = t; break; }
                cum += s_part[t];
            }
            int bsel = seg * (NBUCK / THREADS);
            for (int b = seg * (NBUCK / THREADS) + (NBUCK / THREADS) - 1;
                 b >= seg * (NBUCK / THREADS); b--) {
                cum += s_hist[b];
                if (cum >= KK) { bsel = b; break; }
            }
            s_bsel = bsel;
        }
        __syncthreads();
        const int bsel = s_bsel;
        for (int e = tid; e < NN; e += THREADS) {
            float x = ip[(size_t)e * 5 + 4];
            if ((int)(fkey(x) >> 20) >= bsel) {
                int pos = atomicAdd(&s_cnt, 1);
                if (pos < CAP) s_cand[pos] = make_cand(x, e);
            }
        }
        __syncthreads();
    }

    int C = min(s_cnt, CAP);
    int P = 128;
    while (P < C) P <<= 1;
    if (P > CAP) P = CAP;
    for (int i = C + tid; i < P; i += THREADS) s_cand[i] = 0ull;
    __syncthreads();

    // ---- bitonic sort descending (conf desc, index asc) ----
    for (int k = 2; k <= P; k <<= 1) {
        for (int j = k >> 1; j > 0; j >>= 1) {
            for (int i = tid; i < P; i += THREADS) {
                int ixj = i ^ j;
                if (ixj > i) {
                    unsigned long long va = s_cand[i], vb = s_cand[ixj];
                    bool desc = ((i & k) == 0);
                    if ((va < vb) == desc) { s_cand[i] = vb; s_cand[ixj] = va; }
                }
            }
            __syncthreads();
        }
    }

    // ---- build top-K boxes (clip + fix), cmask, targets ----
    if (tid < KK) {
        unsigned long long v = s_cand[tid];
        unsigned ck = (unsigned)(v >> 32);
        float conf = __uint_as_float(ck ^ 0x80000000u);
        int e = (int)(0xFFFFFFFFu - (unsigned)(v & 0xFFFFFFFFull));
        float o0 = ip[(size_t)e * 5 + 0], o1 = ip[(size_t)e * 5 + 1];
        float o2 = ip[(size_t)e * 5 + 2], o3 = ip[(size_t)e * 5 + 3];
        int a = e % AA;
        int w = (e / AA) % WW;
        int h = e / (AA * WW);
        float px = (1.0f / (1.0f + __expf(-o0)) + (float)w) * STRIDE_;
        float py = (1.0f / (1.0f + __expf(-o1)) + (float)h) * STRIDE_;
        float pw = __expf(o2) * s_anc[a * 2 + 0] * DS_;
        float ph = __expf(o3) * s_anc[a * 2 + 1] * DS_;
        float c0 = px - pw * 0.5f, c1 = py - ph * 0.5f;
        float c2 = px + pw * 0.5f, c3 = py + ph * 0.5f;
        c0 = fminf(fmaxf(c0, 0.0f), DS_); c1 = fminf(fmaxf(c1, 0.0f), DS_);
        c2 = fminf(fmaxf(c2, 0.0f), DS_); c3 = fminf(fmaxf(c3, 0.0f), DS_);
        float x1 = fminf(c0, c2), x2 = fmaxf(c0, c2);
        float y1 = fminf(c1, c3), y2 = fmaxf(c1, c3);
        if (x1 == x2) x2 = x1 + 1.0f;
        if (y1 == y2) y2 = y1 + 1.0f;
        s_bx1[tid] = x1; s_by1[tid] = y1; s_bx2[tid] = x2; s_by2[tid] = y2;
        s_ba[tid] = (x2 - x1) * (y2 - y1);
        s_val[tid] = conf;
        if (conf >= 0.5f) atomicOr(&s_kw[tid >> 5], 1u << (tid & 31));

        const float* tp = tboxes + ((size_t)img * KK + tid) * 4;
        float t0 = fminf(fmaxf(tp[0], 0.0f), DS_);
        float t1 = fminf(fmaxf(tp[1], 0.0f), DS_);
        float t2 = fminf(fmaxf(tp[2], 0.0f), DS_);
        float t3 = fminf(fmaxf(tp[3], 0.0f), DS_);
        float tx1 = fminf(t0, t2), tx2 = fmaxf(t0, t2);
        float ty1 = fminf(t1, t3), ty2 = fmaxf(t1, t3);
        if (tx1 == tx2) tx2 = tx1 + 1.0f;
        if (ty1 == ty2) ty2 = ty1 + 1.0f;
        s_tx1[tid] = tx1; s_ty1[tid] = ty1; s_tx2[tid] = tx2; s_ty2[tid] = ty2;
    }
    __syncthreads();

    // ---- pairwise pred-pred suppression bitmask (parallel) ----
    for (int p = tid; p < KK * KK; p += THREADS) {
        int i = p / KK, j = p % KK;
        if (j > i) {
            float lx = fmaxf(s_bx1[i], s_bx1[j]);
            float ly = fmaxf(s_by1[i], s_by1[j]);
            float rx = fminf(s_bx2[i], s_bx2[j]);
            float ry = fminf(s_by2[i], s_by2[j]);
            float iw = fmaxf(rx - lx, 0.0f), ih = fmaxf(ry - ly, 0.0f);
            float inter = iw * ih;
            float iou = inter / (s_ba[i] + s_ba[j] - inter + EPS_);
            if (iou > 0.5f) atomicOr(&s_sup[i][j >> 5], 1u << (j & 31));
        }
    }
    __syncthreads();

    // ---- greedy NMS sweep (exact reference semantics), serial in thread 0 ----
    if (tid == 0) {
        unsigned kw0 = s_kw[0], kw1 = s_kw[1], kw2 = s_kw[2], kw3 = s_kw[3];
        for (int i = 0; i < KK; i++) {
            unsigned wv = (i < 32) ? kw0 : (i < 64) ? kw1 : (i < 96) ? kw2 : kw3;
            if ((wv >> (i & 31)) & 1u) {
                kw0 &= ~s_sup[i][0]; kw1 &= ~s_sup[i][1];
                kw2 &= ~s_sup[i][2]; kw3 &= ~s_sup[i][3];
            }
        }
        s_kw[0] = kw0; s_kw[1] = kw1; s_kw[2] = kw2; s_kw[3] = kw3;
    }
    __syncthreads();

    // ---- per-target DIoU loss ----
    float diou = 0.0f, lowv = 0.0f, highv = 0.0f;
    if (tid < KK) {
        unsigned kw[4] = { s_kw[0], s_kw[1], s_kw[2], s_kw[3] };
        float tx1 = s_tx1[tid], ty1 = s_ty1[tid], tx2 = s_tx2[tid], ty2 = s_ty2[tid];
        float ta = (tx2 - tx1) * (ty2 - ty1);
        float maxv = -1.0f; int best = 0;
        for (int p = 0; p < KK; p++) {
            float kf = ((kw[p >> 5] >> (p & 31)) & 1u) ? 1.0f : 0.0f;
            float lx = fmaxf(s_bx1[p], tx1);
            float ly = fmaxf(s_by1[p], ty1);
            float rx = fminf(s_bx2[p], tx2);
            float ry = fminf(s_by2[p], ty2);
            float iw = fmaxf(rx - lx, 0.0f), ih = fmaxf(ry - ly, 0.0f);
            float inter = iw * ih;
            float iou = inter / (s_ba[p] + ta - inter + EPS_);
            float v = iou * kf;
            if (v > maxv) { maxv = v; best = p; }   // first occurrence wins
        }
        float max_iou = fmaxf(maxv, 0.0f);
        float pbx1 = s_bx1[best], pby1 = s_by1[best];
        float pbx2 = s_bx2[best], pby2 = s_by2[best];
        float pcx = (pbx1 + pbx2) * 0.5f, pcy = (pby1 + pby2) * 0.5f;
        float tcx = (tx1 + tx2) * 0.5f,  tcy = (ty1 + ty2) * 0.5f;
        float cd = (pcx - tcx) * (pcx - tcx) + (pcy - tcy) * (pcy - tcy);
        float ex1 = fminf(pbx1, tx1), ey1 = fminf(pby1, ty1);
        float ex2 = fmaxf(pbx2, tx2), ey2 = fmaxf(pby2, ty2);
        float dg = (ex2 - ex1) * (ex2 - ex1) + (ey2 - ey1) * (ey2 - ey1);
        diou = 1.0f - (max_iou - cd / (dg + EPS_));

        float kfr = ((s_kw[tid >> 5] >> (tid & 31)) & 1u) ? 1.0f : 0.0f;
        float val = s_val[tid];
        lowv  = fmaxf(-val, 0.0f) * kfr;
        highv = fmaxf(val - 1.0f, 0.0f) * kfr;
    }

    // deterministic reduction: warp shuffles + fixed-order smem combine
    #pragma unroll
    for (int off = 16; off; off >>= 1) {
        diou  += __shfl_down_sync(0xFFFFFFFFu, diou,  off);
        lowv  += __shfl_down_sync(0xFFFFFFFFu, lowv,  off);
        highv += __shfl_down_sync(0xFFFFFFFFu, highv, off);
    }
    if ((tid & 31) == 0) {
        s_red[0][tid >> 5] = diou;
        s_red[1][tid >> 5] = lowv;
        s_red[2][tid >> 5] = highv;
    }
    __syncthreads();
    if (tid == 0) {
        float d = 0.0f, l = 0.0f, h = 0.0f;
        #pragma unroll
        for (int w = 0; w < THREADS / 32; w++) {
            d += s_red[0][w]; l += s_red[1][w]; h += s_red[2][w];
        }
        float cnt = (float)(__popc(s_kw[0]) + __popc(s_kw[1]) +
                            __popc(s_kw[2]) + __popc(s_kw[3]));
        g_scratch[img * 4 + 0] = d;
        g_scratch[img * 4 + 1] = l;
        g_scratch[img * 4 + 2] = h;
        g_scratch[img * 4 + 3] = cnt;
        g_cnt[img] = 0;                 // reset for next graph replay
        __threadfence();
        unsigned t = atomicAdd(&g_done, 1u);
        s_last = (t == BB - 1) ? 1 : 0;
    }
    __syncthreads();

    // ---- last block performs the global reduction (fused finalize) ----
    if (s_last) {
        float d = 0.0f, l = 0.0f, h = 0.0f, c = 0.0f;
        if (tid < BB) {
            d = g_scratch[tid * 4 + 0];
            l = g_scratch[tid * 4 + 1];
            h = g_scratch[tid * 4 + 2];
            c = g_scratch[tid * 4 + 3];
        }
        #pragma unroll
        for (int off = 16; off; off >>= 1) {
            d += __shfl_down_sync(0xFFFFFFFFu, d, off);
            l += __shfl_down_sync(0xFFFFFFFFu, l, off);
            h += __shfl_down_sync(0xFFFFFFFFu, h, off);
            c += __shfl_down_sync(0xFFFFFFFFu, c, off);
        }
        if ((tid & 31) == 0) {
            s_red[0][tid >> 5] = d;
            s_red[1][tid >> 5] = l;
            s_red[2][tid >> 5] = h;
            s_part[tid >> 5]   = __float_as_uint(c);
        }
        __syncthreads();
        if (tid == 0) {
            float D = 0.0f, L = 0.0f, H = 0.0f, Cn = 0.0f;
            #pragma unroll
            for (int w = 0; w < THREADS / 32; w++) {
                D += s_red[0][w]; L += s_red[1][w]; H += s_red[2][w];
                Cn += __uint_as_float(s_part[w]);
            }
            float n = fmaxf(Cn, 1.0f);
            out[0] = D / (float)(BB * KK) + L / n + 0.5f * (H / n);
            g_done = 0;                 // reset for next graph replay
        }
    }
}

extern "C" void kernel_launch(void* const* d_in, const int* in_sizes, int n_in,
                              void* d_out, int out_size)
{
    const float* output  = (const float*)d_in[0];   // (128,64,64,9,5) fp32
    const float* tboxes  = (const float*)d_in[1];   // (128,100,4) fp32
    const float* anchors = (const float*)d_in[2];   // (9,2) fp32
    float* out = (float*)d_out;

    collect_kernel<<<BB * SPLIT, THREADS>>>(output);
    loss_kernel<<<BB, THREADS>>>(output, tboxes, anchors, out);
}

// round 6
// speedup vs baseline: 1.3330x; 1.0166x over previous
#include <cuda_runtime.h>
#include <math.h>

#define BB 128
#define HH 64
#define WW 64
#define AA 9
#define NN (HH*WW*AA)           // 36864 predictions per image
#define KK 100
#define NBUCK 2048
#define CAP 1024                // candidate capacity per image
#define SPLIT 9                 // collect CTAs per image
#define NSEG (NN/SPLIT)         // 4096 elements per collect CTA
#define THREADS 256
#define DS_ 1024.0f
#define STRIDE_ 64.0f
#define EPS_ 1e-7f
#define T0_ 1.25f               // static logit collect-threshold (fallback-guarded)

// globals (zero-initialized at load; kernel self-resets for graph replay)
__device__ unsigned long long g_cand[BB][CAP];
__device__ int g_cnt[BB];
__device__ unsigned g_segdone[BB];
__device__ float g_scratch[BB * 4];
__device__ unsigned g_done;

__device__ __forceinline__ unsigned fkey(float x) {
    unsigned u = __float_as_uint(x);
    return (u & 0x80000000u) ? ~u : (u | 0x80000000u);
}

__device__ __forceinline__ unsigned long long make_cand(float x, int e) {
    float conf = 1.0f / (1.0f + __expf(-x));           // conf in (0,1)
    unsigned ck = __float_as_uint(conf) ^ 0x80000000u; // order-preserving (conf>0)
    return ((unsigned long long)ck << 32) | (unsigned)(0xFFFFFFFFu - (unsigned)e);
}

__global__ __launch_bounds__(THREADS)
void fused_kernel(const float* __restrict__ out5,
                  const float* __restrict__ tboxes,
                  const float* __restrict__ anchors,
                  float* __restrict__ out)
{
    __shared__ union {
        unsigned hist[NBUCK];                  // fallback only (8KB)
        unsigned long long cand[CAP];          // 8KB
    } u;
    __shared__ unsigned s_part[THREADS];
    __shared__ float s_bx1[KK], s_by1[KK], s_bx2[KK], s_by2[KK], s_ba[KK], s_val[KK];
    __shared__ float s_tx1[KK], s_ty1[KK], s_tx2[KK], s_ty2[KK];
    __shared__ unsigned long long s_best[KK];
    __shared__ unsigned s_sup[KK][4];
    __shared__ unsigned s_kw[4];
    __shared__ int s_cnt, s_bsel, s_go, s_last;
    __shared__ float s_anc[AA * 2];
    __shared__ float s_red[3][THREADS / 32];

    const int tid = threadIdx.x;
    const int img = blockIdx.x / SPLIT;
    const int seg = blockIdx.x % SPLIT;
    const float* __restrict__ ip = out5 + (size_t)img * NN * 5;

    // ================= phase 1: segment collection (all CTAs) =================
    {
        const int base = seg * NSEG;
        #pragma unroll 8
        for (int i = tid; i < NSEG; i += THREADS) {
            int e = base + i;
            float x = __ldg(&ip[(size_t)e * 5 + 4]);
            if (x > T0_) {
                int q = atomicAdd(&g_cnt[img], 1);
                if (q < CAP) g_cand[img][q] = make_cand(x, e);
            }
        }
    }
    __threadfence();                 // each thread fences its own candidate stores
    __syncthreads();
    if (tid == 0) {
        unsigned q = atomicAdd(&g_segdone[img], 1u);
        s_go = (q == SPLIT - 1) ? 1 : 0;
    }
    __syncthreads();
    if (!s_go) return;               // non-last CTAs exit; last runs the tail

    // ================= phase 2: per-image tail (1 CTA per image) ==============
    if (tid == 0) g_segdone[img] = 0;            // reset for next graph replay
    __threadfence();                             // acquire candidates from peers

    if (tid < AA * 2) s_anc[tid] = anchors[tid];
    if (tid == 0) { s_kw[0] = s_kw[1] = s_kw[2] = s_kw[3] = 0; }
    for (int i = tid; i < KK * 4; i += THREADS) ((unsigned*)s_sup)[i] = 0;
    if (tid < KK) s_best[tid] = 0ull;

    const int gcnt = g_cnt[img];
    if (tid == 0) s_cnt = gcnt;
    {
        int C0 = min(gcnt, CAP);
        for (int i = tid; i < C0; i += THREADS) u.cand[i] = g_cand[img][i];
    }
    __syncthreads();

    // ---- fallback: exact histogram top-K (never taken for typical inputs) ----
    if (gcnt < KK || gcnt > CAP) {
        for (int i = tid; i < NBUCK; i += THREADS) u.hist[i] = 0;
        if (tid == 0) s_cnt = 0;
        __syncthreads();
        for (int e = tid; e < NN; e += THREADS) {
            float x = ip[(size_t)e * 5 + 4];
            atomicAdd(&u.hist[fkey(x) >> 21], 1u);
        }
        __syncthreads();
        {
            unsigned s = 0;
            int base = tid * (NBUCK / THREADS);
            #pragma unroll
            for (int j = 0; j < NBUCK / THREADS; j++) s += u.hist[base + j];
            s_part[tid] = s;
        }
        __syncthreads();
        if (tid == 0) {
            unsigned cum = 0; int sg = 0;
            for (int t = THREADS - 1; t >= 0; t--) {
                if (cum + s_part[t] >= KK) { sg = t; break; }
                cum += s_part[t];
            }
            int bsel = sg * (NBUCK / THREADS);
            for (int b = sg * (NBUCK / THREADS) + (NBUCK / THREADS) - 1;
                 b >= sg * (NBUCK / THREADS); b--) {
                cum += u.hist[b];
                if (cum >= KK) { bsel = b; break; }
            }
            s_bsel = bsel;
        }
        __syncthreads();
        const int bsel = s_bsel;
        // collect overwrites u.cand (hist no longer needed)
        for (int e = tid; e < NN; e += THREADS) {
            float x = ip[(size_t)e * 5 + 4];
            if ((int)(fkey(x) >> 21) >= bsel) {
                int pos = atomicAdd(&s_cnt, 1);
                if (pos < CAP) u.cand[pos] = make_cand(x, e);
            }
        }
        __syncthreads();
    }

    int C = min(s_cnt, CAP);
    int P = 128;
    while (P < C) P <<= 1;
    if (P > CAP) P = CAP;
    for (int i = C + tid; i < P; i += THREADS) u.cand[i] = 0ull;
    __syncthreads();

    // ---- bitonic sort descending (conf desc, index asc) ----
    for (int k = 2; k <= P; k <<= 1) {
        for (int j = k >> 1; j > 0; j >>= 1) {
            for (int i = tid; i < P; i += THREADS) {
                int ixj = i ^ j;
                if (ixj > i) {
                    unsigned long long va = u.cand[i], vb = u.cand[ixj];
                    bool desc = ((i & k) == 0);
                    if ((va < vb) == desc) { u.cand[i] = vb; u.cand[ixj] = va; }
                }
            }
            __syncthreads();
        }
    }

    // ---- build top-K boxes (clip + fix), cmask, targets ----
    if (tid < KK) {
        unsigned long long v = u.cand[tid];
        unsigned ck = (unsigned)(v >> 32);
        float conf = __uint_as_float(ck ^ 0x80000000u);
        int e = (int)(0xFFFFFFFFu - (unsigned)(v & 0xFFFFFFFFull));
        float o0 = ip[(size_t)e * 5 + 0], o1 = ip[(size_t)e * 5 + 1];
        float o2 = ip[(size_t)e * 5 + 2], o3 = ip[(size_t)e * 5 + 3];
        int a = e % AA;
        int w = (e / AA) % WW;
        int h = e / (AA * WW);
        float px = (1.0f / (1.0f + __expf(-o0)) + (float)w) * STRIDE_;
        float py = (1.0f / (1.0f + __expf(-o1)) + (float)h) * STRIDE_;
        float pw = __expf(o2) * s_anc[a * 2 + 0] * DS_;
        float ph = __expf(o3) * s_anc[a * 2 + 1] * DS_;
        float c0 = px - pw * 0.5f, c1 = py - ph * 0.5f;
        float c2 = px + pw * 0.5f, c3 = py + ph * 0.5f;
        c0 = fminf(fmaxf(c0, 0.0f), DS_); c1 = fminf(fmaxf(c1, 0.0f), DS_);
        c2 = fminf(fmaxf(c2, 0.0f), DS_); c3 = fminf(fmaxf(c3, 0.0f), DS_);
        float x1 = fminf(c0, c2), x2 = fmaxf(c0, c2);
        float y1 = fminf(c1, c3), y2 = fmaxf(c1, c3);
        if (x1 == x2) x2 = x1 + 1.0f;
        if (y1 == y2) y2 = y1 + 1.0f;
        s_bx1[tid] = x1; s_by1[tid] = y1; s_bx2[tid] = x2; s_by2[tid] = y2;
        s_ba[tid] = (x2 - x1) * (y2 - y1);
        s_val[tid] = conf;
        if (conf >= 0.5f) atomicOr(&s_kw[tid >> 5], 1u << (tid & 31));

        const float* tp = tboxes + ((size_t)img * KK + tid) * 4;
        float t0 = fminf(fmaxf(tp[0], 0.0f), DS_);
        float t1 = fminf(fmaxf(tp[1], 0.0f), DS_);
        float t2 = fminf(fmaxf(tp[2], 0.0f), DS_);
        float t3 = fminf(fmaxf(tp[3], 0.0f), DS_);
        float tx1 = fminf(t0, t2), tx2 = fmaxf(t0, t2);
        float ty1 = fminf(t1, t3), ty2 = fmaxf(t1, t3);
        if (tx1 == tx2) tx2 = tx1 + 1.0f;
        if (ty1 == ty2) ty2 = ty1 + 1.0f;
        s_tx1[tid] = tx1; s_ty1[tid] = ty1; s_tx2[tid] = tx2; s_ty2[tid] = ty2;
    }
    __syncthreads();

    // ---- pairwise pred-pred suppression bitmask (parallel, fast div) ----
    for (int p = tid; p < KK * KK; p += THREADS) {
        int i = p / KK, j = p % KK;
        if (j > i) {
            float lx = fmaxf(s_bx1[i], s_bx1[j]);
            float ly = fmaxf(s_by1[i], s_by1[j]);
            float rx = fminf(s_bx2[i], s_bx2[j]);
            float ry = fminf(s_by2[i], s_by2[j]);
            float iw = fmaxf(rx - lx, 0.0f), ih = fmaxf(ry - ly, 0.0f);
            float inter = iw * ih;
            float iou = __fdividef(inter, s_ba[i] + s_ba[j] - inter + EPS_);
            if (iou > 0.5f) atomicOr(&s_sup[i][j >> 5], 1u << (j & 31));
        }
    }
    __syncthreads();

    // ---- greedy NMS sweep (exact reference semantics), serial in thread 0 ----
    if (tid == 0) {
        const uint4* supv = (const uint4*)s_sup;
        unsigned kw0 = s_kw[0], kw1 = s_kw[1], kw2 = s_kw[2], kw3 = s_kw[3];
        #pragma unroll 4
        for (int i = 0; i < KK; i++) {
            uint4 r = supv[i];
            unsigned wv = (i < 32) ? kw0 : (i < 64) ? kw1 : (i < 96) ? kw2 : kw3;
            if ((wv >> (i & 31)) & 1u) {
                kw0 &= ~r.x; kw1 &= ~r.y; kw2 &= ~r.z; kw3 &= ~r.w;
            }
        }
        s_kw[0] = kw0; s_kw[1] = kw1; s_kw[2] = kw2; s_kw[3] = kw3;
    }
    __syncthreads();

    // ---- per-target max-IoU argmax: all 256 threads over 10000 pairs ----
    // key = (iou_bits << 32) | ~p  -> max gives max iou; ties -> smallest p
    {
        unsigned kw[4] = { s_kw[0], s_kw[1], s_kw[2], s_kw[3] };
        for (int q = tid; q < KK * KK; q += THREADS) {
            int t = q / KK, p = q % KK;
            float kf = ((kw[p >> 5] >> (p & 31)) & 1u) ? 1.0f : 0.0f;
            float lx = fmaxf(s_bx1[p], s_tx1[t]);
            float ly = fmaxf(s_by1[p], s_ty1[t]);
            float rx = fminf(s_bx2[p], s_tx2[t]);
            float ry = fminf(s_by2[p], s_ty2[t]);
            float iw = fmaxf(rx - lx, 0.0f), ih = fmaxf(ry - ly, 0.0f);
            float inter = iw * ih;
            float ta = (s_tx2[t] - s_tx1[t]) * (s_ty2[t] - s_ty1[t]);
            float iou = __fdividef(inter, s_ba[p] + ta - inter + EPS_);
            float v = iou * kf;                  // v >= 0 -> bits monotonic
            unsigned long long key = ((unsigned long long)__float_as_uint(v) << 32)
                                   | (unsigned)(0xFFFFFFFFu - (unsigned)p);
            atomicMax(&s_best[t], key);
        }
    }
    __syncthreads();

    // ---- per-target DIoU + penalty terms ----
    float diou = 0.0f, lowv = 0.0f, highv = 0.0f;
    if (tid < KK) {
        unsigned long long key = s_best[tid];
        float max_iou = fmaxf(__uint_as_float((unsigned)(key >> 32)), 0.0f);
        int best = (int)(0xFFFFFFFFu - (unsigned)(key & 0xFFFFFFFFull));
        float tx1 = s_tx1[tid], ty1 = s_ty1[tid], tx2 = s_tx2[tid], ty2 = s_ty2[tid];
        float pbx1 = s_bx1[best], pby1 = s_by1[best];
        float pbx2 = s_bx2[best], pby2 = s_by2[best];
        float pcx = (pbx1 + pbx2) * 0.5f, pcy = (pby1 + pby2) * 0.5f;
        float tcx = (tx1 + tx2) * 0.5f,  tcy = (ty1 + ty2) * 0.5f;
        float cd = (pcx - tcx) * (pcx - tcx) + (pcy - tcy) * (pcy - tcy);
        float ex1 = fminf(pbx1, tx1), ey1 = fminf(pby1, ty1);
        float ex2 = fmaxf(pbx2, tx2), ey2 = fmaxf(pby2, ty2);
        float dg = (ex2 - ex1) * (ex2 - ex1) + (ey2 - ey1) * (ey2 - ey1);
        diou = 1.0f - (max_iou - __fdividef(cd, dg + EPS_));

        float kfr = ((s_kw[tid >> 5] >> (tid & 31)) & 1u) ? 1.0f : 0.0f;
        float val = s_val[tid];
        lowv  = fmaxf(-val, 0.0f) * kfr;
        highv = fmaxf(val - 1.0f, 0.0f) * kfr;
    }

    // deterministic reduction: warp shuffles + fixed-order smem combine
    #pragma unroll
    for (int off = 16; off; off >>= 1) {
        diou  += __shfl_down_sync(0xFFFFFFFFu, diou,  off);
        lowv  += __shfl_down_sync(0xFFFFFFFFu, lowv,  off);
        highv += __shfl_down_sync(0xFFFFFFFFu, highv, off);
    }
    if ((tid & 31) == 0) {
        s_red[0][tid >> 5] = diou;
        s_red[1][tid >> 5] = lowv;
        s_red[2][tid >> 5] = highv;
    }
    __syncthreads();
    if (tid == 0) {
        float d = 0.0f, l = 0.0f, h = 0.0f;
        #pragma unroll
        for (int w = 0; w < THREADS / 32; w++) {
            d += s_red[0][w]; l += s_red[1][w]; h += s_red[2][w];
        }
        float cnt = (float)(__popc(s_kw[0]) + __popc(s_kw[1]) +
                            __popc(s_kw[2]) + __popc(s_kw[3]));
        g_scratch[img * 4 + 0] = d;
        g_scratch[img * 4 + 1] = l;
        g_scratch[img * 4 + 2] = h;
        g_scratch[img * 4 + 3] = cnt;
        g_cnt[img] = 0;                 // reset for next graph replay
        __threadfence();
        unsigned t = atomicAdd(&g_done, 1u);
        s_last = (t == BB - 1) ? 1 : 0;
    }
    __syncthreads();

    // ---- last image's tail CTA performs the global finalize ----
    if (s_last) {
        __threadfence();
        float d = 0.0f, l = 0.0f, h = 0.0f, c = 0.0f;
        if (tid < BB) {
            d = g_scratch[tid * 4 + 0];
            l = g_scratch[tid * 4 + 1];
            h = g_scratch[tid * 4 + 2];
            c = g_scratch[tid * 4 + 3];
        }
        #pragma unroll
        for (int off = 16; off; off >>= 1) {
            d += __shfl_down_sync(0xFFFFFFFFu, d, off);
            l += __shfl_down_sync(0xFFFFFFFFu, l, off);
            h += __shfl_down_sync(0xFFFFFFFFu, h, off);
            c += __shfl_down_sync(0xFFFFFFFFu, c, off);
        }
        if ((tid & 31) == 0) {
            s_red[0][tid >> 5] = d;
            s_red[1][tid >> 5] = l;
            s_red[2][tid >> 5] = h;
            s_part[tid >> 5]   = __float_as_uint(c);
        }
        __syncthreads();
        if (tid == 0) {
            float D = 0.0f, L = 0.0f, H = 0.0f, Cn = 0.0f;
            #pragma unroll
            for (int w = 0; w < THREADS / 32; w++) {
                D += s_red[0][w]; L += s_red[1][w]; H += s_red[2][w];
                Cn += __uint_as_float(s_part[w]);
            }
            float n = fmaxf(Cn, 1.0f);
            out[0] = D / (float)(BB * KK) + L / n + 0.5f * (H / n);
            g_done = 0;                 // reset for next graph replay
        }
    }
}

extern "C" void kernel_launch(void* const* d_in, const int* in_sizes, int n_in,
                              void* d_out, int out_size)
{
    const float* output  = (const float*)d_in[0];   // (128,64,64,9,5) fp32
    const float* tboxes  = (const float*)d_in[1];   // (128,100,4) fp32
    const float* anchors = (const float*)d_in[2];   // (9,2) fp32
    float* out = (float*)d_out;

    fused_kernel<<<BB * SPLIT, THREADS>>>(output, tboxes, anchors, out);
}